// round 13
// baseline (speedup 1.0000x reference)
#include <cuda_runtime.h>

typedef unsigned long long u64;

// ---------------- device scratch ----------------
__device__ float g_KG[1024 * 128];       // [ij][c] (written by gemm1 bx==0 blocks)
__device__ float g_W[1024 * 1024];       // weights
__device__ float g_part[8 * 1024 * 128]; // GEMM2 k-split partials (split 8)
__device__ float g_denp[16 * 1024];      // den partials per gemm1 n-block (16)

// ---------------- packed f32x2 helpers ----------------
__device__ __forceinline__ u64 pack2(float lo, float hi) {
    u64 r; asm("mov.b64 %0,{%1,%2};" : "=l"(r) : "f"(lo), "f"(hi)); return r;
}
__device__ __forceinline__ void unpack2(u64 v, float& lo, float& hi) {
    asm("mov.b64 {%0,%1},%2;" : "=f"(lo), "=f"(hi) : "l"(v));
}
__device__ __forceinline__ void fma2(u64& c, u64 a, u64 b) {
    asm("fma.rn.f32x2 %0,%1,%2,%0;" : "+l"(c) : "l"(a), "l"(b));
}

// ---------------- GEMM1 with in-block param computation ----------------
// Block (m0=bx*64, n0=by*64), 256 threads.
// Phase P: compute invSigma / -2*mu*invSigma for the block's 64 ij into
//          Bsf[128][64] smem + sCc[64]; bx==0 blocks also write g_KG.
// Phase G: q = Xext @ Bsf with A-only double buffering (R6 inner loop).
__global__ __launch_bounds__(256) void gemm1_kernel(const float* __restrict__ X,
                                                    const float* __restrict__ Lam,
                                                    const float* __restrict__ Mu0,
                                                    const float* __restrict__ Mu1,
                                                    const float* __restrict__ S0,
                                                    const float* __restrict__ S1,
                                                    const float* __restrict__ tptr) {
    __shared__ float Bsf[128][64];    // 32 KB: [k'][ij-local]
    __shared__ float As[2][16][64];   // 8 KB
    __shared__ float sCc4[4][64];     // 1 KB
    __shared__ float sCc[64];

    const int tid = threadIdx.x;
    const int tx = tid & 15, ty = tid >> 4;
    const int m0 = blockIdx.x * 64, n0 = blockIdx.y * 64;
    const float t = *tptr, uu = 1.0f - t;

    // ======== Phase P: params for ij in [n0, n0+64) ========
    {
        const int ijl = tid & 63;          // this thread's local ij
        const int kg  = tid >> 6;          // k-group 0..3
        const int ij  = n0 + ijl;
        const int i = ij >> 5, j = ij & 31;
        const bool emit_kg = (blockIdx.x == 0);
        float csum = 0.0f;
        #pragma unroll
        for (int it = 0; it < 16; it++) {
            int k = kg * 16 + it;
            float s0 = S0[i * 64 + k], s1 = S1[j * 64 + k];
            float m0v = Mu0[i * 64 + k], m1v = Mu1[j * 64 + k];
            float Ds = sqrtf(4.0f * s0 * s1 + 0.0625f);
            float Cs = 0.5f * (Ds - 0.25f);
            float mu = uu * m0v + t * m1v;
            float Sig = uu * uu * s0 + t * t * s1 + 2.0f * t * uu * (Cs + 0.125f);
            float St = t * s1 + uu * Cs - (uu * s0 + t * Cs) - 0.25f * t;
            float invS = 1.0f / Sig;
            Bsf[k][ijl]      = invS;
            Bsf[64 + k][ijl] = -2.0f * mu * invS;
            if (emit_kg) {
                float Kv = St * invS;
                g_KG[ij * 128 + k]      = Kv;
                g_KG[ij * 128 + 64 + k] = (m1v - m0v) - Kv * mu;
            }
            csum += mu * mu * invS + __logf(Sig);
        }
        sCc4[kg][ijl] = csum;
    }
    __syncthreads();
    if (tid < 64) sCc[tid] = (sCc4[0][tid] + sCc4[1][tid]) + (sCc4[2][tid] + sCc4[3][tid]);

    // ======== Phase G ========
    u64 acc[2][4];
    #pragma unroll
    for (int i = 0; i < 2; i++)
        #pragma unroll
        for (int j = 0; j < 4; j++) acc[i][j] = 0ULL;

    const int rA = tid & 63, sA = tid >> 6;

    // stage A chunk 0 (X cols 0..15, squared)
    {
        float4 v = *(const float4*)&X[(m0 + rA) * 64 + sA * 4];
        v.x *= v.x; v.y *= v.y; v.z *= v.z; v.w *= v.w;
        As[0][sA * 4 + 0][rA] = v.x; As[0][sA * 4 + 1][rA] = v.y;
        As[0][sA * 4 + 2][rA] = v.z; As[0][sA * 4 + 3][rA] = v.w;
    }
    __syncthreads();   // covers Bsf/sCc readiness too

    #pragma unroll 1
    for (int c = 0; c < 8; c++) {
        const int p = c & 1;
        float4 va;
        if (c < 7) {
            int cc = c + 1;
            va = *(const float4*)&X[(m0 + rA) * 64 + (cc & 3) * 16 + sA * 4];
            if (cc < 4) { va.x *= va.x; va.y *= va.y; va.z *= va.z; va.w *= va.w; }
        }
        #pragma unroll
        for (int k = 0; k < 16; k++) {
            ulonglong2 a = *(const ulonglong2*)&As[p][k][ty * 4];
            float4 b = *(const float4*)&Bsf[c * 16 + k][tx * 4];
            u64 b0 = pack2(b.x, b.x), b1 = pack2(b.y, b.y);
            u64 b2 = pack2(b.z, b.z), b3 = pack2(b.w, b.w);
            fma2(acc[0][0], a.x, b0); fma2(acc[1][0], a.y, b0);
            fma2(acc[0][1], a.x, b1); fma2(acc[1][1], a.y, b1);
            fma2(acc[0][2], a.x, b2); fma2(acc[1][2], a.y, b2);
            fma2(acc[0][3], a.x, b3); fma2(acc[1][3], a.y, b3);
        }
        if (c < 7) {
            __syncthreads();   // protect As[p^1] (being read by no one: only A buffers flip)
            As[p ^ 1][sA * 4 + 0][rA] = va.x; As[p ^ 1][sA * 4 + 1][rA] = va.y;
            As[p ^ 1][sA * 4 + 2][rA] = va.z; As[p ^ 1][sA * 4 + 3][rA] = va.w;
            __syncthreads();
        }
    }

    // ---- epilogue (R6 semantics; Cc from smem) ----
    float4 cc4 = *(const float4*)&sCc[tx * 4];
    float4 ll4 = *(const float4*)&Lam[n0 + tx * 4];
    float ccs[4] = {cc4.x, cc4.y, cc4.z, cc4.w};
    float lls[4] = {ll4.x, ll4.y, ll4.z, ll4.w};

    #pragma unroll
    for (int mp = 0; mp < 2; mp++) {
        float wlo[4], whi[4];
        #pragma unroll
        for (int j = 0; j < 4; j++) {
            float qlo, qhi;
            unpack2(acc[mp][j], qlo, qhi);
            wlo[j] = __expf(fminf(fmaxf(-0.5f * (qlo + ccs[j]), -50.0f), 50.0f)) * lls[j];
            whi[j] = __expf(fminf(fmaxf(-0.5f * (qhi + ccs[j]), -50.0f), 50.0f)) * lls[j];
        }
        int mlo = m0 + ty * 4 + 2 * mp;
        *(float4*)&g_W[mlo * 1024 + n0 + tx * 4]       = *(float4*)&wlo[0];
        *(float4*)&g_W[(mlo + 1) * 1024 + n0 + tx * 4] = *(float4*)&whi[0];
        float rlo = (wlo[0] + wlo[1]) + (wlo[2] + wlo[3]);
        float rhi = (whi[0] + whi[1]) + (whi[2] + whi[3]);
        #pragma unroll
        for (int o = 1; o < 16; o <<= 1) {
            rlo += __shfl_xor_sync(0xffffffffu, rlo, o);
            rhi += __shfl_xor_sync(0xffffffffu, rhi, o);
        }
        if (tx == 0) {
            g_denp[blockIdx.y * 1024 + mlo]     = rlo;
            g_denp[blockIdx.y * 1024 + mlo + 1] = rhi;
        }
    }
}

// ---------------- GEMM2: part = W @ KG, split 8 (exact R6) ----------------
__global__ __launch_bounds__(256) void gemm2_kernel() {
    __shared__ float As[2][16][64];
    __shared__ float Bs[2][16][64];

    const int tid = threadIdx.x;
    const int tx = tid & 15, ty = tid >> 4;
    const int m0 = blockIdx.x * 64, n0 = blockIdx.y * 64;
    const int k0 = blockIdx.z * 128;

    const int rA = tid & 63, sA = tid >> 6;
    const int rB = tid >> 4, cB = (tid & 15) * 4;

    u64 acc[2][4];
    #pragma unroll
    for (int i = 0; i < 2; i++)
        #pragma unroll
        for (int j = 0; j < 4; j++) acc[i][j] = 0ULL;

    {
        float4 v = *(const float4*)&g_W[(m0 + rA) * 1024 + k0 + sA * 4];
        As[0][sA * 4 + 0][rA] = v.x; As[0][sA * 4 + 1][rA] = v.y;
        As[0][sA * 4 + 2][rA] = v.z; As[0][sA * 4 + 3][rA] = v.w;
        *(float4*)&Bs[0][rB][cB] = *(const float4*)&g_KG[(k0 + rB) * 128 + n0 + cB];
    }
    __syncthreads();

    #pragma unroll 1
    for (int c = 0; c < 8; c++) {
        const int p = c & 1;
        float4 va, vb;
        if (c < 7) {
            int cc = c + 1;
            va = *(const float4*)&g_W[(m0 + rA) * 1024 + k0 + cc * 16 + sA * 4];
            vb = *(const float4*)&g_KG[(k0 + cc * 16 + rB) * 128 + n0 + cB];
        }
        #pragma unroll
        for (int k = 0; k < 16; k++) {
            ulonglong2 a = *(const ulonglong2*)&As[p][k][ty * 4];
            float4 b = *(const float4*)&Bs[p][k][tx * 4];
            u64 b0 = pack2(b.x, b.x), b1 = pack2(b.y, b.y);
            u64 b2 = pack2(b.z, b.z), b3 = pack2(b.w, b.w);
            fma2(acc[0][0], a.x, b0); fma2(acc[1][0], a.y, b0);
            fma2(acc[0][1], a.x, b1); fma2(acc[1][1], a.y, b1);
            fma2(acc[0][2], a.x, b2); fma2(acc[1][2], a.y, b2);
            fma2(acc[0][3], a.x, b3); fma2(acc[1][3], a.y, b3);
        }
        if (c < 7) {
            As[p ^ 1][sA * 4 + 0][rA] = va.x; As[p ^ 1][sA * 4 + 1][rA] = va.y;
            As[p ^ 1][sA * 4 + 2][rA] = va.z; As[p ^ 1][sA * 4 + 3][rA] = va.w;
            *(float4*)&Bs[p ^ 1][rB][cB] = vb;
            __syncthreads();
        }
    }

    const int s = blockIdx.z;
    #pragma unroll
    for (int mp = 0; mp < 2; mp++) {
        float vlo[4], vhi[4];
        #pragma unroll
        for (int j = 0; j < 4; j++) unpack2(acc[mp][j], vlo[j], vhi[j]);
        int mlo = m0 + ty * 4 + 2 * mp;
        *(float4*)&g_part[(s * 1024 + mlo) * 128 + n0 + tx * 4]     = *(float4*)&vlo[0];
        *(float4*)&g_part[(s * 1024 + mlo + 1) * 128 + n0 + tx * 4] = *(float4*)&vhi[0];
    }
}

// ---------------- final: warp per batch row, split 8 (exact R6) ----------------
__global__ __launch_bounds__(128) void final_kernel(const float* __restrict__ X,
                                                    float* __restrict__ out) {
    const int tid = threadIdx.x;
    const int b = blockIdx.x * 4 + (tid >> 5);
    const int lane = tid & 31;
    const int l = lane & 15;
    const int h = lane >> 4;
    const int k4 = l * 4;

    float4 A = make_float4(0.f, 0.f, 0.f, 0.f);
    float4 Bv = make_float4(0.f, 0.f, 0.f, 0.f);
    #pragma unroll
    for (int si = 0; si < 4; si++) {
        int s = h * 4 + si;
        float4 a = *(const float4*)&g_part[(s * 1024 + b) * 128 + k4];
        float4 q = *(const float4*)&g_part[(s * 1024 + b) * 128 + 64 + k4];
        A.x += a.x; A.y += a.y; A.z += a.z; A.w += a.w;
        Bv.x += q.x; Bv.y += q.y; Bv.z += q.z; Bv.w += q.w;
    }
    A.x += __shfl_xor_sync(0xffffffffu, A.x, 16);
    A.y += __shfl_xor_sync(0xffffffffu, A.y, 16);
    A.z += __shfl_xor_sync(0xffffffffu, A.z, 16);
    A.w += __shfl_xor_sync(0xffffffffu, A.w, 16);
    Bv.x += __shfl_xor_sync(0xffffffffu, Bv.x, 16);
    Bv.y += __shfl_xor_sync(0xffffffffu, Bv.y, 16);
    Bv.z += __shfl_xor_sync(0xffffffffu, Bv.z, 16);
    Bv.w += __shfl_xor_sync(0xffffffffu, Bv.w, 16);

    float d = g_denp[l * 1024 + b];
    #pragma unroll
    for (int o = 1; o < 16; o <<= 1) d += __shfl_xor_sync(0xffffffffu, d, o);
    float inv = 1.0f / d;

    if (h == 0) {
        float4 x = *(const float4*)&X[b * 64 + k4];
        float4 o4;
        o4.x = (x.x * A.x + Bv.x) * inv;
        o4.y = (x.y * A.y + Bv.y) * inv;
        o4.z = (x.z * A.z + Bv.z) * inv;
        o4.w = (x.w * A.w + Bv.w) * inv;
        *(float4*)&out[b * 64 + k4] = o4;
    }
}

// ---------------- launch: 3 kernels ----------------
extern "C" void kernel_launch(void* const* d_in, const int* in_sizes, int n_in,
                              void* d_out, int out_size) {
    const float* X   = (const float*)d_in[0];
    const float* Mu0 = (const float*)d_in[1];
    const float* Mu1 = (const float*)d_in[2];
    const float* S0  = (const float*)d_in[3];
    const float* S1  = (const float*)d_in[4];
    const float* Lam = (const float*)d_in[5];
    const float* t   = (const float*)d_in[6];
    float* out = (float*)d_out;

    gemm1_kernel<<<dim3(16, 16), 256>>>(X, Lam, Mu0, Mu1, S0, S1, t);
    gemm2_kernel<<<dim3(16, 2, 8), 256>>>();
    final_kernel<<<256, 128>>>(X, out);
}

// round 14
// speedup vs baseline: 1.5549x; 1.5549x over previous
#include <cuda_runtime.h>

typedef unsigned long long u64;

// ---------------- device scratch ----------------
__device__ float g_KG[1024 * 128];       // [ij][c] (written by gemm1 bx==0 blocks)
__device__ float g_W[1024 * 1024];       // weights
__device__ float g_part[8 * 1024 * 128]; // GEMM2 k-split partials (split 8)
__device__ float g_denp[16 * 1024];      // den partials per gemm1 n-block (16)

// ---------------- packed f32x2 helpers ----------------
__device__ __forceinline__ u64 pack2(float lo, float hi) {
    u64 r; asm("mov.b64 %0,{%1,%2};" : "=l"(r) : "f"(lo), "f"(hi)); return r;
}
__device__ __forceinline__ void unpack2(u64 v, float& lo, float& hi) {
    asm("mov.b64 {%0,%1},%2;" : "=f"(lo), "=f"(hi) : "l"(v));
}
__device__ __forceinline__ void fma2(u64& c, u64 a, u64 b) {
    asm("fma.rn.f32x2 %0,%1,%2,%0;" : "+l"(c) : "l"(a), "l"(b));
}

// ---------------- GEMM1 with fused param computation ----------------
// Block (m0=bx*64, n0=by*64), 256 threads.
// Phase P (warp-per-ij, lane=k; coalesced LDG): params for the block's 64 ij
//   -> Bsf[128][68] (k-major, pad 68) + sCc[64]; bx==0 blocks also emit g_KG.
// Phase G: exactly R6's GEMM loop; B read from Bsf, A double-buffered.
__global__ __launch_bounds__(256) void gemm1_kernel(const float* __restrict__ X,
                                                    const float* __restrict__ Lam,
                                                    const float* __restrict__ Mu0,
                                                    const float* __restrict__ Mu1,
                                                    const float* __restrict__ S0,
                                                    const float* __restrict__ S1,
                                                    const float* __restrict__ tptr) {
    __shared__ float Bsf[128][68];    // 34 KB
    __shared__ float As[2][16][64];   // 8 KB
    __shared__ float sCc[64];

    const int tid = threadIdx.x;
    const int tx = tid & 15, ty = tid >> 4;
    const int m0 = blockIdx.x * 64, n0 = blockIdx.y * 64;
    const float t = *tptr, uu = 1.0f - t;

    // ======== Phase P ========
    {
        const int w = tid >> 5, lane = tid & 31;
        const bool emit_kg = (blockIdx.x == 0);
        #pragma unroll 1
        for (int rr = 0; rr < 8; rr++) {
            const int ijl = w * 8 + rr;
            const int ij = n0 + ijl;
            const int i = ij >> 5, j = ij & 31;
            float csum = 0.0f;
            #pragma unroll
            for (int kk = 0; kk < 2; kk++) {
                int k = kk * 32 + lane;
                float s0 = S0[i * 64 + k], s1 = S1[j * 64 + k];
                float m0v = Mu0[i * 64 + k], m1v = Mu1[j * 64 + k];
                float Ds = sqrtf(4.0f * s0 * s1 + 0.0625f);
                float Cs = 0.5f * (Ds - 0.25f);
                float mu = uu * m0v + t * m1v;
                float Sig = uu * uu * s0 + t * t * s1 + 2.0f * t * uu * (Cs + 0.125f);
                float St = t * s1 + uu * Cs - (uu * s0 + t * Cs) - 0.25f * t;
                float invS = 1.0f / Sig;
                Bsf[k][ijl]      = invS;
                Bsf[64 + k][ijl] = -2.0f * mu * invS;
                if (emit_kg) {
                    float Kv = St * invS;
                    g_KG[ij * 128 + k]      = Kv;
                    g_KG[ij * 128 + 64 + k] = (m1v - m0v) - Kv * mu;
                }
                csum += mu * mu * invS + __logf(Sig);
            }
            #pragma unroll
            for (int o = 16; o > 0; o >>= 1) csum += __shfl_xor_sync(0xffffffffu, csum, o);
            if (lane == 0) sCc[ijl] = csum;
        }
    }

    // ======== Phase G ========
    u64 acc[2][4];
    #pragma unroll
    for (int i = 0; i < 2; i++)
        #pragma unroll
        for (int j = 0; j < 4; j++) acc[i][j] = 0ULL;

    const int rA = tid & 63, sA = tid >> 6;

    // stage A chunk 0 (X cols 0..15, squared)
    {
        float4 v = *(const float4*)&X[(m0 + rA) * 64 + sA * 4];
        v.x *= v.x; v.y *= v.y; v.z *= v.z; v.w *= v.w;
        As[0][sA * 4 + 0][rA] = v.x; As[0][sA * 4 + 1][rA] = v.y;
        As[0][sA * 4 + 2][rA] = v.z; As[0][sA * 4 + 3][rA] = v.w;
    }
    __syncthreads();   // Bsf + sCc + As[0] all ready

    #pragma unroll 1
    for (int c = 0; c < 8; c++) {
        const int p = c & 1;
        float4 va;
        if (c < 7) {
            int cc = c + 1;
            va = *(const float4*)&X[(m0 + rA) * 64 + (cc & 3) * 16 + sA * 4];
            if (cc < 4) { va.x *= va.x; va.y *= va.y; va.z *= va.z; va.w *= va.w; }
        }
        #pragma unroll
        for (int k = 0; k < 16; k++) {
            ulonglong2 a = *(const ulonglong2*)&As[p][k][ty * 4];
            float4 b = *(const float4*)&Bsf[c * 16 + k][tx * 4];
            u64 b0 = pack2(b.x, b.x), b1 = pack2(b.y, b.y);
            u64 b2 = pack2(b.z, b.z), b3 = pack2(b.w, b.w);
            fma2(acc[0][0], a.x, b0); fma2(acc[1][0], a.y, b0);
            fma2(acc[0][1], a.x, b1); fma2(acc[1][1], a.y, b1);
            fma2(acc[0][2], a.x, b2); fma2(acc[1][2], a.y, b2);
            fma2(acc[0][3], a.x, b3); fma2(acc[1][3], a.y, b3);
        }
        if (c < 7) {
            As[p ^ 1][sA * 4 + 0][rA] = va.x; As[p ^ 1][sA * 4 + 1][rA] = va.y;
            As[p ^ 1][sA * 4 + 2][rA] = va.z; As[p ^ 1][sA * 4 + 3][rA] = va.w;
            __syncthreads();
        }
    }

    // ---- epilogue (R6 semantics; Cc from smem) ----
    float4 cc4 = *(const float4*)&sCc[tx * 4];
    float4 ll4 = *(const float4*)&Lam[n0 + tx * 4];
    float ccs[4] = {cc4.x, cc4.y, cc4.z, cc4.w};
    float lls[4] = {ll4.x, ll4.y, ll4.z, ll4.w};

    #pragma unroll
    for (int mp = 0; mp < 2; mp++) {
        float wlo[4], whi[4];
        #pragma unroll
        for (int j = 0; j < 4; j++) {
            float qlo, qhi;
            unpack2(acc[mp][j], qlo, qhi);
            wlo[j] = __expf(fminf(fmaxf(-0.5f * (qlo + ccs[j]), -50.0f), 50.0f)) * lls[j];
            whi[j] = __expf(fminf(fmaxf(-0.5f * (qhi + ccs[j]), -50.0f), 50.0f)) * lls[j];
        }
        int mlo = m0 + ty * 4 + 2 * mp;
        *(float4*)&g_W[mlo * 1024 + n0 + tx * 4]       = *(float4*)&wlo[0];
        *(float4*)&g_W[(mlo + 1) * 1024 + n0 + tx * 4] = *(float4*)&whi[0];
        float rlo = (wlo[0] + wlo[1]) + (wlo[2] + wlo[3]);
        float rhi = (whi[0] + whi[1]) + (whi[2] + whi[3]);
        #pragma unroll
        for (int o = 1; o < 16; o <<= 1) {
            rlo += __shfl_xor_sync(0xffffffffu, rlo, o);
            rhi += __shfl_xor_sync(0xffffffffu, rhi, o);
        }
        if (tx == 0) {
            g_denp[blockIdx.y * 1024 + mlo]     = rlo;
            g_denp[blockIdx.y * 1024 + mlo + 1] = rhi;
        }
    }
}

// ---------------- GEMM2: part = W @ KG, split 8 (exact R6) ----------------
__global__ __launch_bounds__(256) void gemm2_kernel() {
    __shared__ float As[2][16][64];
    __shared__ float Bs[2][16][64];

    const int tid = threadIdx.x;
    const int tx = tid & 15, ty = tid >> 4;
    const int m0 = blockIdx.x * 64, n0 = blockIdx.y * 64;
    const int k0 = blockIdx.z * 128;

    const int rA = tid & 63, sA = tid >> 6;
    const int rB = tid >> 4, cB = (tid & 15) * 4;

    u64 acc[2][4];
    #pragma unroll
    for (int i = 0; i < 2; i++)
        #pragma unroll
        for (int j = 0; j < 4; j++) acc[i][j] = 0ULL;

    {
        float4 v = *(const float4*)&g_W[(m0 + rA) * 1024 + k0 + sA * 4];
        As[0][sA * 4 + 0][rA] = v.x; As[0][sA * 4 + 1][rA] = v.y;
        As[0][sA * 4 + 2][rA] = v.z; As[0][sA * 4 + 3][rA] = v.w;
        *(float4*)&Bs[0][rB][cB] = *(const float4*)&g_KG[(k0 + rB) * 128 + n0 + cB];
    }
    __syncthreads();

    #pragma unroll 1
    for (int c = 0; c < 8; c++) {
        const int p = c & 1;
        float4 va, vb;
        if (c < 7) {
            int cc = c + 1;
            va = *(const float4*)&g_W[(m0 + rA) * 1024 + k0 + cc * 16 + sA * 4];
            vb = *(const float4*)&g_KG[(k0 + cc * 16 + rB) * 128 + n0 + cB];
        }
        #pragma unroll
        for (int k = 0; k < 16; k++) {
            ulonglong2 a = *(const ulonglong2*)&As[p][k][ty * 4];
            float4 b = *(const float4*)&Bs[p][k][tx * 4];
            u64 b0 = pack2(b.x, b.x), b1 = pack2(b.y, b.y);
            u64 b2 = pack2(b.z, b.z), b3 = pack2(b.w, b.w);
            fma2(acc[0][0], a.x, b0); fma2(acc[1][0], a.y, b0);
            fma2(acc[0][1], a.x, b1); fma2(acc[1][1], a.y, b1);
            fma2(acc[0][2], a.x, b2); fma2(acc[1][2], a.y, b2);
            fma2(acc[0][3], a.x, b3); fma2(acc[1][3], a.y, b3);
        }
        if (c < 7) {
            As[p ^ 1][sA * 4 + 0][rA] = va.x; As[p ^ 1][sA * 4 + 1][rA] = va.y;
            As[p ^ 1][sA * 4 + 2][rA] = va.z; As[p ^ 1][sA * 4 + 3][rA] = va.w;
            *(float4*)&Bs[p ^ 1][rB][cB] = vb;
            __syncthreads();
        }
    }

    const int s = blockIdx.z;
    #pragma unroll
    for (int mp = 0; mp < 2; mp++) {
        float vlo[4], vhi[4];
        #pragma unroll
        for (int j = 0; j < 4; j++) unpack2(acc[mp][j], vlo[j], vhi[j]);
        int mlo = m0 + ty * 4 + 2 * mp;
        *(float4*)&g_part[(s * 1024 + mlo) * 128 + n0 + tx * 4]     = *(float4*)&vlo[0];
        *(float4*)&g_part[(s * 1024 + mlo + 1) * 128 + n0 + tx * 4] = *(float4*)&vhi[0];
    }
}

// ---------------- final: warp per batch row, split 8 (exact R6) ----------------
__global__ __launch_bounds__(128) void final_kernel(const float* __restrict__ X,
                                                    float* __restrict__ out) {
    const int tid = threadIdx.x;
    const int b = blockIdx.x * 4 + (tid >> 5);
    const int lane = tid & 31;
    const int l = lane & 15;
    const int h = lane >> 4;
    const int k4 = l * 4;

    float4 A = make_float4(0.f, 0.f, 0.f, 0.f);
    float4 Bv = make_float4(0.f, 0.f, 0.f, 0.f);
    #pragma unroll
    for (int si = 0; si < 4; si++) {
        int s = h * 4 + si;
        float4 a = *(const float4*)&g_part[(s * 1024 + b) * 128 + k4];
        float4 q = *(const float4*)&g_part[(s * 1024 + b) * 128 + 64 + k4];
        A.x += a.x; A.y += a.y; A.z += a.z; A.w += a.w;
        Bv.x += q.x; Bv.y += q.y; Bv.z += q.z; Bv.w += q.w;
    }
    A.x += __shfl_xor_sync(0xffffffffu, A.x, 16);
    A.y += __shfl_xor_sync(0xffffffffu, A.y, 16);
    A.z += __shfl_xor_sync(0xffffffffu, A.z, 16);
    A.w += __shfl_xor_sync(0xffffffffu, A.w, 16);
    Bv.x += __shfl_xor_sync(0xffffffffu, Bv.x, 16);
    Bv.y += __shfl_xor_sync(0xffffffffu, Bv.y, 16);
    Bv.z += __shfl_xor_sync(0xffffffffu, Bv.z, 16);
    Bv.w += __shfl_xor_sync(0xffffffffu, Bv.w, 16);

    float d = g_denp[l * 1024 + b];
    #pragma unroll
    for (int o = 1; o < 16; o <<= 1) d += __shfl_xor_sync(0xffffffffu, d, o);
    float inv = 1.0f / d;

    if (h == 0) {
        float4 x = *(const float4*)&X[b * 64 + k4];
        float4 o4;
        o4.x = (x.x * A.x + Bv.x) * inv;
        o4.y = (x.y * A.y + Bv.y) * inv;
        o4.z = (x.z * A.z + Bv.z) * inv;
        o4.w = (x.w * A.w + Bv.w) * inv;
        *(float4*)&out[b * 64 + k4] = o4;
    }
}

// ---------------- launch: 3 kernels ----------------
extern "C" void kernel_launch(void* const* d_in, const int* in_sizes, int n_in,
                              void* d_out, int out_size) {
    const float* X   = (const float*)d_in[0];
    const float* Mu0 = (const float*)d_in[1];
    const float* Mu1 = (const float*)d_in[2];
    const float* S0  = (const float*)d_in[3];
    const float* S1  = (const float*)d_in[4];
    const float* Lam = (const float*)d_in[5];
    const float* t   = (const float*)d_in[6];
    float* out = (float*)d_out;

    gemm1_kernel<<<dim3(16, 16), 256>>>(X, Lam, Mu0, Mu1, S0, S1, t);
    gemm2_kernel<<<dim3(16, 2, 8), 256>>>();
    final_kernel<<<256, 128>>>(X, out);
}